// round 1
// baseline (speedup 1.0000x reference)
#include <cuda_runtime.h>
#include <cuda_bf16.h>
#include <math.h>

// ---------------- problem constants ----------------
#define NB 32          // B*T
#define D64 64
#define HH 64
#define WW 64
#define HW 4096
#define C2 128
#define BB 4
#define TT 8

// output regions (floats)
#define OUT_RE   0
#define OUT_IM   8388608
#define HOUT_RE  16777216
#define HOUT_IM  (16777216 + 1048576)
#define FLUX_RE  (16777216 + 2097152)
#define FLUX_IM  (FLUX_RE + 256)

// ---------------- scratch (device globals; no allocation) ----------------
__device__ float g_xn[NB * C2 * HW];          // layernormed, (n,c,h,w)
__device__ float g_xsp_re[NB * D64 * HW];     // (n,d,h,w)
__device__ float g_xsp_im[NB * D64 * HW];
__device__ float g_xeig_re[NB * HW * D64];    // (n,h,w,e)
__device__ float g_xeig_im[NB * HW * D64];
__device__ float g_y_re[NB * HW * D64];       // (n,h,w,e)
__device__ float g_y_im[NB * HW * D64];
__device__ float g_z[NB * HW * C2];           // rows: [re(64), im(64)]
__device__ float g_sum_re[BB * TT * D64];     // 2048 (for x_mean)
__device__ float g_sum_im[BB * TT * D64];
__device__ float g_gate[BB * TT * D64];
__device__ float g_src_re[BB * TT * D64];
__device__ float g_src_im[BB * TT * D64];
__device__ float g_ah_re[D64], g_ah_im[D64];
__device__ float g_ch_re[D64], g_ch_im[D64];

// ---------------- kernel 1: layernorm over 128 channels ----------------
__global__ void k_ln(const float* __restrict__ xre, const float* __restrict__ xim,
                     const float* __restrict__ gamma, const float* __restrict__ beta) {
    int n = blockIdx.x >> 6, h = blockIdx.x & 63;
    int w = threadIdx.x;  // 64 threads
    if (blockIdx.x == 0) {
        for (int i = w; i < BB * TT * D64; i += 64) { g_sum_re[i] = 0.f; g_sum_im[i] = 0.f; }
    }
    int base0 = n * 262144 + h * 64 + w;   // (n, d=0, h, w); d-stride 4096
    float s = 0.f, s2 = 0.f;
    #pragma unroll 4
    for (int c = 0; c < 64; c++) { float v = xre[base0 + c * 4096]; s += v; s2 += v * v; }
    #pragma unroll 4
    for (int c = 0; c < 64; c++) { float v = xim[base0 + c * 4096]; s += v; s2 += v * v; }
    float mu  = s * (1.f / 128.f);
    float var = s2 * (1.f / 128.f) - mu * mu;
    float inv = rsqrtf(var + 1e-5f);
    int ob = n * (C2 * HW) + h * 64 + w;
    #pragma unroll 4
    for (int c = 0; c < 128; c++) {
        float v = (c < 64) ? xre[base0 + c * 4096] : xim[base0 + (c - 64) * 4096];
        g_xn[ob + c * 4096] = (v - mu) * inv * gamma[c] + beta[c];
    }
}

// ---------------- kernel 2: conv 3x3 SAME + bias + metric + residual -> xsp ----------------
__global__ void __launch_bounds__(256) k_conv(
        const float* __restrict__ xre, const float* __restrict__ xim,
        const float* __restrict__ cw, const float* __restrict__ cb,
        const float* __restrict__ metric) {
    int n = blockIdx.x >> 6, h = blockIdx.x & 63;
    int tid = threadIdx.x;
    int cog = tid >> 4;       // 16 groups * 8 co = 128
    int wg  = tid & 15;       // 16 groups * 4 w  = 64
    int w4 = wg * 4;
    __shared__ float s_in[3 * 68];
    __shared__ float s_wt[1152];
    float acc[8][4];
    #pragma unroll
    for (int a = 0; a < 8; a++)
        #pragma unroll
        for (int j = 0; j < 4; j++) acc[a][j] = 0.f;

    for (int ci = 0; ci < 128; ci++) {
        __syncthreads();
        for (int i = tid; i < 3 * 66; i += 256) {
            int r = i / 66, c = i % 66;
            int hh = h + r - 1, ww = c - 1;
            float v = 0.f;
            if (hh >= 0 && hh < 64 && ww >= 0 && ww < 64)
                v = g_xn[((n * 128 + ci) * 64 + hh) * 64 + ww];
            s_in[r * 68 + c] = v;
        }
        for (int i = tid; i < 1152; i += 256) {
            int co = i / 9, k = i % 9;
            s_wt[i] = cw[(co * 128 + ci) * 9 + k];
        }
        __syncthreads();
        float in[3][6];
        #pragma unroll
        for (int r = 0; r < 3; r++)
            #pragma unroll
            for (int c = 0; c < 6; c++) in[r][c] = s_in[r * 68 + w4 + c];
        #pragma unroll
        for (int a = 0; a < 8; a++) {
            const float* wp = &s_wt[(cog * 8 + a) * 9];
            float w00 = wp[0], w01 = wp[1], w02 = wp[2];
            float w10 = wp[3], w11 = wp[4], w12 = wp[5];
            float w20 = wp[6], w21 = wp[7], w22 = wp[8];
            #pragma unroll
            for (int j = 0; j < 4; j++) {
                acc[a][j] += w00 * in[0][j] + w01 * in[0][j + 1] + w02 * in[0][j + 2]
                           + w10 * in[1][j] + w11 * in[1][j + 1] + w12 * in[1][j + 2]
                           + w20 * in[2][j] + w21 * in[2][j + 1] + w22 * in[2][j + 2];
            }
        }
    }
    #pragma unroll
    for (int a = 0; a < 8; a++) {
        int co = cog * 8 + a;
        float bias = cb[co];
        #pragma unroll
        for (int j = 0; j < 4; j++) {
            int w = w4 + j;
            float val = (acc[a][j] + bias) * metric[h * 64 + w];
            if (co < 64) {
                int idx = ((n * 64 + co) * 64 + h) * 64 + w;
                g_xsp_re[idx] = xre[idx] + val;
            } else {
                int idx = ((n * 64 + (co - 64)) * 64 + h) * 64 + w;
                g_xsp_im[idx] = xim[idx] + val;
            }
        }
    }
}

// ---------------- kernel 3: x_eig = xsp @ E (complex) + H,W-mean partial sums ----------------
__global__ void __launch_bounds__(256) k_eig(const float* __restrict__ Er, const float* __restrict__ Ei) {
    extern __shared__ float sm[];
    float* sEr = sm;                 // 4096
    float* sEi = sEr + 4096;         // 4096
    float* sXr = sEi + 4096;         // 64*65  [d][w] padded
    float* sXi = sXr + 64 * 65;
    float* sOut = sXi + 64 * 65;     // 64*129 [w][e] padded
    int n = blockIdx.x >> 6, h = blockIdx.x & 63;
    int tid = threadIdx.x;
    int w = tid & 63;
    int eg = tid >> 6;               // 4 groups * 16 e
    for (int i = tid; i < 4096; i += 256) {
        sEr[i] = Er[i]; sEi[i] = Ei[i];
        int d = i >> 6, ww = i & 63;
        int gi = ((n * 64 + d) * 64 + h) * 64 + ww;
        sXr[d * 65 + ww] = g_xsp_re[gi];
        sXi[d * 65 + ww] = g_xsp_im[gi];
    }
    __syncthreads();
    float ar[16], ai[16];
    #pragma unroll
    for (int k = 0; k < 16; k++) { ar[k] = 0.f; ai[k] = 0.f; }
    for (int d = 0; d < 64; d++) {
        float xr = sXr[d * 65 + w], xi = sXi[d * 65 + w];
        #pragma unroll
        for (int k = 0; k < 16; k++) {
            int e = eg * 16 + k;
            float er = sEr[d * 64 + e], ei = sEi[d * 64 + e];
            ar[k] += xr * er - xi * ei;
            ai[k] += xr * ei + xi * er;
        }
    }
    // mean partial: reduce over w within each warp, then atomic
    #pragma unroll
    for (int k = 0; k < 16; k++) {
        float sr = ar[k], si = ai[k];
        #pragma unroll
        for (int off = 16; off > 0; off >>= 1) {
            sr += __shfl_xor_sync(0xffffffff, sr, off);
            si += __shfl_xor_sync(0xffffffff, si, off);
        }
        if ((tid & 31) == 0) {
            atomicAdd(&g_sum_re[n * 64 + eg * 16 + k], sr);
            atomicAdd(&g_sum_im[n * 64 + eg * 16 + k], si);
        }
    }
    int base = (n * 64 + h) * 4096;
    #pragma unroll
    for (int k = 0; k < 16; k++) sOut[w * 129 + eg * 16 + k] = ar[k];
    __syncthreads();
    for (int i = tid; i < 4096; i += 256) g_xeig_re[base + i] = sOut[(i >> 6) * 129 + (i & 63)];
    __syncthreads();
    #pragma unroll
    for (int k = 0; k < 16; k++) sOut[w * 129 + eg * 16 + k] = ai[k];
    __syncthreads();
    for (int i = tid; i < 4096; i += 256) g_xeig_im[base + i] = sOut[(i >> 6) * 129 + (i & 63)];
}

// ---------------- kernel 4: flux scan, source, gate, a_h/c_h (single block) ----------------
__global__ void k_flux(const float* __restrict__ dtp,
                       const float* __restrict__ lfre, const float* __restrict__ lfim,
                       const float* __restrict__ lhre, const float* __restrict__ lhim,
                       const float* __restrict__ fpre, const float* __restrict__ fpim,
                       const float* __restrict__ Wsr, const float* __restrict__ Wsi,
                       const float* __restrict__ Wg,  const float* __restrict__ bg,
                       float* __restrict__ out) {
    __shared__ float s_ffr[BB * TT * D64];
    __shared__ float s_ffi[BB * TT * D64];
    int tid = threadIdx.x;           // 256
    int b = tid >> 6, d = tid & 63;
    float dtv = dtp[0];

    // flux recurrence per (b,d)
    float lfr = -fabsf(lfre[d]), lfi = lfim[d];
    float efac = expf(lfr * dtv);
    float afr = efac * cosf(lfi * dtv), afi = efac * sinf(lfi * dtv);
    float den = lfr * lfr + lfi * lfi;
    float nr = afr - 1.f, ni = afi;
    float cfr = (nr * lfr + ni * lfi) / den;
    float cfi = (ni * lfr - nr * lfi) / den;
    float fr = fpre[b * 64 + d], fi = fpim[b * 64 + d];
    for (int t = 0; t < TT; t++) {
        s_ffr[(b * TT + t) * 64 + d] = fr;   // flux_forcing[t]
        s_ffi[(b * TT + t) * 64 + d] = fi;
        float xmr = g_sum_re[(b * TT + t) * 64 + d] * (1.f / 4096.f);
        float xmi = g_sum_im[(b * TT + t) * 64 + d] * (1.f / 4096.f);
        float ur = xmr * cfr - xmi * cfi;
        float ui = xmr * cfi + xmi * cfr;
        float nfr = afr * fr - afi * fi + ur;
        float nfi = afr * fi + afi * fr + ui;
        fr = nfr; fi = nfi;
    }
    out[FLUX_RE + b * 64 + d] = fr;
    out[FLUX_IM + b * 64 + d] = fi;

    if (tid < 64) {  // a_h, c_h per d
        float lr = -fabsf(lhre[tid]), li = lhim[tid];
        float e2 = expf(lr * dtv);
        float ahr = e2 * cosf(li * dtv), ahi = e2 * sinf(li * dtv);
        float dd = lr * lr + li * li;
        float mr = ahr - 1.f, mi = ahi;
        g_ah_re[tid] = ahr; g_ah_im[tid] = ahi;
        g_ch_re[tid] = (mr * lr + mi * li) / dd;
        g_ch_im[tid] = (mi * lr - mr * li) / dd;
    }
    __syncthreads();

    // source & gate: thread (b, e)
    int e = d;
    for (int t = 0; t < TT; t++) {
        float sr = 0.f, si = 0.f, ga = bg[e];
        for (int dd = 0; dd < 64; dd++) {
            float ffr = s_ffr[(b * TT + t) * 64 + dd];
            float ffi = s_ffi[(b * TT + t) * 64 + dd];
            float wr = Wsr[dd * 64 + e], wi = Wsi[dd * 64 + e];
            sr += ffr * wr - ffi * wi;
            si += ffr * wi + ffi * wr;
            ga += ffr * Wg[dd * 64 + e];
        }
        int q = (b * TT + t) * 64 + e;
        g_src_re[q] = sr;
        g_src_im[q] = si;
        g_gate[q] = 1.f / (1.f + expf(-ga));
    }
}

// ---------------- kernel 5: T-scan for y + h_out ----------------
__global__ void k_scan(const float* __restrict__ hpr, const float* __restrict__ hpi,
                       float* __restrict__ out) {
    int gid = blockIdx.x * 256 + threadIdx.x;    // 1048576 threads
    int e = gid & 63;
    int pos = gid >> 6;                          // b*4096 + hw
    int b = pos >> 12, hw = pos & 4095;
    float ahr = g_ah_re[e], ahi = g_ah_im[e];
    float chr = g_ch_re[e], chi = g_ch_im[e];
    float yr = hpr[gid], yi = hpi[gid];
    #pragma unroll
    for (int t = 0; t < TT; t++) {
        int idx = ((b * TT + t) * 4096 + hw) * 64 + e;
        float xr = g_xeig_re[idx], xi = g_xeig_im[idx];
        int q = (b * TT + t) * 64 + e;
        float gg = g_gate[q];
        float sr = g_src_re[q], si = g_src_im[q];
        float fr = xr * gg + sr * (1.f - gg);
        float fi = xi * gg + si * (1.f - gg);
        float ur = fr * chr - fi * chi;
        float ui = fr * chi + fi * chr;
        float nyr = ahr * yr - ahi * yi + ur;
        float nyi = ahr * yi + ahi * yr + ui;
        yr = nyr; yi = nyi;
        g_y_re[idx] = yr; g_y_im[idx] = yi;
    }
    out[HOUT_RE + gid] = yr;
    out[HOUT_IM + gid] = yi;
}

// ---------------- kernel 6: y_dec = y @ Edec (complex) -> z rows ----------------
__global__ void __launch_bounds__(256) k_dec(const float* __restrict__ Er, const float* __restrict__ Ei) {
    extern __shared__ float sm[];
    float* sEr = sm;
    float* sEi = sEr + 4096;
    float* sYr = sEi + 4096;          // [w][d] padded 65
    float* sYi = sYr + 64 * 65;
    float* sOut = sYi + 64 * 65;      // [w][c] padded 129
    int n = blockIdx.x >> 6, h = blockIdx.x & 63;
    int tid = threadIdx.x;
    int w = tid & 63;
    int eg = tid >> 6;
    int base = (n * 64 + h) * 4096;
    for (int i = tid; i < 4096; i += 256) {
        sEr[i] = Er[i]; sEi[i] = Ei[i];
        sYr[(i >> 6) * 65 + (i & 63)] = g_y_re[base + i];
        sYi[(i >> 6) * 65 + (i & 63)] = g_y_im[base + i];
    }
    __syncthreads();
    float ar[16], ai[16];
    #pragma unroll
    for (int k = 0; k < 16; k++) { ar[k] = 0.f; ai[k] = 0.f; }
    for (int d = 0; d < 64; d++) {
        float xr = sYr[w * 65 + d], xi = sYi[w * 65 + d];
        #pragma unroll
        for (int k = 0; k < 16; k++) {
            int e = eg * 16 + k;
            float er = sEr[d * 64 + e], ei = sEi[d * 64 + e];
            ar[k] += xr * er - xi * ei;
            ai[k] += xr * ei + xi * er;
        }
    }
    #pragma unroll
    for (int k = 0; k < 16; k++) {
        sOut[w * 129 + eg * 16 + k] = ar[k];
        sOut[w * 129 + 64 + eg * 16 + k] = ai[k];
    }
    __syncthreads();
    int zb = (n * 64 + h) * 8192;
    for (int i = tid; i < 8192; i += 256)
        g_z[zb + i] = sOut[(i >> 7) * 129 + (i & 127)];
}

// ---------------- kernel 7: fused FFN + final residual output ----------------
__global__ void __launch_bounds__(256) k_ffn(const float* __restrict__ w1, const float* __restrict__ b1,
                                             const float* __restrict__ w2, const float* __restrict__ b2,
                                             float* __restrict__ out) {
    extern __shared__ float sm[];
    float* zs  = sm;                  // 32*129 rows [r][c]
    float* w1s = zs + 32 * 129;       // 128*64   [k][j]
    float* hid = w1s + 8192;          // 32*64    [r][j]
    float* w2s = hid + 2048;          // 64*128   [k][c]
    float* ob  = w2s + 8192;          // 128*33   [c][r]
    int blk = blockIdx.x;             // 4096
    int half = blk & 1;
    int nh = blk >> 1;
    int n = nh >> 6, h = nh & 63;
    int w0 = half * 32;
    int tid = threadIdx.x;
    int rowbase = (n * 64 + h) * 64 + w0;

    for (int i = tid; i < 32 * 128; i += 256)
        zs[(i >> 7) * 129 + (i & 127)] = g_z[(rowbase + (i >> 7)) * 128 + (i & 127)];

    int jg = tid & 15, rg = tid >> 4;     // hidden phase: rows 2rg,2rg+1; j = jg+16*jj
    int cg = tid & 31, rg2 = tid >> 5;    // acc phase: rows rg2*4+rr; c = cg+32*cc
    float acc[4][4];
    #pragma unroll
    for (int a = 0; a < 4; a++)
        #pragma unroll
        for (int c = 0; c < 4; c++) acc[a][c] = 0.f;

    for (int hc = 0; hc < 8; hc++) {
        __syncthreads();
        for (int i = tid; i < 8192; i += 256)
            w1s[i] = w1[(i >> 6) * 512 + hc * 64 + (i & 63)];
        for (int i = tid; i < 8192; i += 256)
            w2s[i] = w2[(hc * 64 + (i >> 7)) * 128 + (i & 127)];
        __syncthreads();

        float hv[2][4];
        #pragma unroll
        for (int rr = 0; rr < 2; rr++)
            #pragma unroll
            for (int jj = 0; jj < 4; jj++) hv[rr][jj] = 0.f;
        for (int k = 0; k < 128; k++) {
            float z0 = zs[(2 * rg) * 129 + k];
            float z1 = zs[(2 * rg + 1) * 129 + k];
            #pragma unroll
            for (int jj = 0; jj < 4; jj++) {
                float wv = w1s[k * 64 + jg + 16 * jj];
                hv[0][jj] += z0 * wv;
                hv[1][jj] += z1 * wv;
            }
        }
        #pragma unroll
        for (int rr = 0; rr < 2; rr++)
            #pragma unroll
            for (int jj = 0; jj < 4; jj++) {
                int j = jg + 16 * jj;
                float x = hv[rr][jj] + b1[hc * 64 + j];
                float t = tanhf(0.7978845608028654f * (x + 0.044715f * x * x * x));
                hid[(2 * rg + rr) * 64 + j] = 0.5f * x * (1.f + t);
            }
        __syncthreads();
        for (int k = 0; k < 64; k++) {
            float h0 = hid[(rg2 * 4 + 0) * 64 + k];
            float h1 = hid[(rg2 * 4 + 1) * 64 + k];
            float h2 = hid[(rg2 * 4 + 2) * 64 + k];
            float h3 = hid[(rg2 * 4 + 3) * 64 + k];
            #pragma unroll
            for (int cc = 0; cc < 4; cc++) {
                float wv = w2s[k * 128 + cg + 32 * cc];
                acc[0][cc] += h0 * wv;
                acc[1][cc] += h1 * wv;
                acc[2][cc] += h2 * wv;
                acc[3][cc] += h3 * wv;
            }
        }
    }
    __syncthreads();
    #pragma unroll
    for (int rr = 0; rr < 4; rr++)
        #pragma unroll
        for (int cc = 0; cc < 4; cc++)
            ob[(cg + 32 * cc) * 33 + rg2 * 4 + rr] = acc[rr][cc];
    __syncthreads();
    for (int i = tid; i < 4096; i += 256) {
        int c = i >> 5, w = i & 31;
        float o = ob[c * 33 + w] + b2[c];
        float zv = zs[w * 129 + c];
        int d = c & 63;
        int gidx = ((n * 64 + d) * 64 + h) * 64 + w0 + w;
        if (c < 64) out[OUT_RE + gidx] = g_xsp_re[gidx] + zv + o;
        else        out[OUT_IM + gidx] = g_xsp_im[gidx] + zv + o;
    }
}

// ---------------- launch ----------------
extern "C" void kernel_launch(void* const* d_in, const int* in_sizes, int n_in,
                              void* d_out, int out_size) {
    const float* x_re      = (const float*)d_in[0];
    const float* x_im      = (const float*)d_in[1];
    const float* h_prev_re = (const float*)d_in[2];
    const float* h_prev_im = (const float*)d_in[3];
    const float* flux_p_re = (const float*)d_in[4];
    const float* flux_p_im = (const float*)d_in[5];
    const float* dt        = (const float*)d_in[6];
    const float* ln_gamma  = (const float*)d_in[7];
    const float* ln_beta   = (const float*)d_in[8];
    const float* conv_w    = (const float*)d_in[9];
    const float* conv_b    = (const float*)d_in[10];
    const float* metric    = (const float*)d_in[11];
    const float* E_re      = (const float*)d_in[12];
    const float* E_im      = (const float*)d_in[13];
    const float* Edec_re   = (const float*)d_in[14];
    const float* Edec_im   = (const float*)d_in[15];
    const float* lam_h_re  = (const float*)d_in[16];
    const float* lam_h_im  = (const float*)d_in[17];
    const float* lam_f_re  = (const float*)d_in[18];
    const float* lam_f_im  = (const float*)d_in[19];
    const float* W_src_re  = (const float*)d_in[20];
    const float* W_src_im  = (const float*)d_in[21];
    const float* W_gate    = (const float*)d_in[22];
    const float* b_gate    = (const float*)d_in[23];
    const float* ffn_w1    = (const float*)d_in[24];
    const float* ffn_b1    = (const float*)d_in[25];
    const float* ffn_w2    = (const float*)d_in[26];
    const float* ffn_b2    = (const float*)d_in[27];
    float* out = (float*)d_out;

    const int smem_eig = (4096 * 2 + 64 * 65 * 2 + 64 * 129) * 4;   // 99072
    const int smem_ffn = (32 * 129 + 8192 + 2048 + 8192 + 128 * 33) * 4;  // 107136
    cudaFuncSetAttribute(k_eig, cudaFuncAttributeMaxDynamicSharedMemorySize, smem_eig);
    cudaFuncSetAttribute(k_dec, cudaFuncAttributeMaxDynamicSharedMemorySize, smem_eig);
    cudaFuncSetAttribute(k_ffn, cudaFuncAttributeMaxDynamicSharedMemorySize, smem_ffn);

    k_ln  <<<NB * HH, 64>>>(x_re, x_im, ln_gamma, ln_beta);
    k_conv<<<NB * HH, 256>>>(x_re, x_im, conv_w, conv_b, metric);
    k_eig <<<NB * HH, 256, smem_eig>>>(E_re, E_im);
    k_flux<<<1, 256>>>(dt, lam_f_re, lam_f_im, lam_h_re, lam_h_im,
                       flux_p_re, flux_p_im, W_src_re, W_src_im, W_gate, b_gate, out);
    k_scan<<<4096, 256>>>(h_prev_re, h_prev_im, out);
    k_dec <<<NB * HH, 256, smem_eig>>>(Edec_re, Edec_im);
    k_ffn <<<NB * HH * 2, 256, smem_ffn>>>(ffn_w1, ffn_b1, ffn_w2, ffn_b2, out);
}